// round 7
// baseline (speedup 1.0000x reference)
#include <cuda_runtime.h>
#include <cstdint>

#define BATCH 64
#define SEQ   512
#define HID   300
#define UN    512
#define G3    1536
#define NBLK  128
#define UPB   4   // hidden units per block (NBLK*UPB == UN)

// ---- scratch (device globals: allocation is forbidden) ----
__device__ float g_xg [SEQ * G3 * BATCH];   // input projections [s][col][b] (reused by both layers)
__device__ float g_y0 [SEQ * BATCH * UN];   // layer0 outputs [s][b][u]
__device__ float g_h  [2][BATCH * UN];      // ping-pong hidden state
__device__ unsigned g_arrive[NBLK];         // distributed barrier slots

__device__ __forceinline__ float sigm(float x) { return 1.f / (1.f + __expf(-x)); }

__device__ __forceinline__ uint32_t smem_u32(const void* p) {
    uint32_t a;
    asm("{ .reg .u64 t; cvta.to.shared.u64 t, %1; cvt.u32.u64 %0, t; }" : "=r"(a) : "l"(p));
    return a;
}
// load 16B from shared as two packed f32x2 (no pack instructions needed)
__device__ __forceinline__ void lds2(unsigned long long& a, unsigned long long& b, uint32_t addr) {
    asm volatile("ld.shared.v2.u64 {%0,%1},[%2];" : "=l"(a), "=l"(b) : "r"(addr));
}
// packed dual-FMA: d.lo += a.lo*b.lo ; d.hi += a.hi*b.hi
__device__ __forceinline__ void fma2(unsigned long long& d, unsigned long long a, unsigned long long b) {
    asm volatile("fma.rn.f32x2 %0, %1, %2, %0;" : "+l"(d) : "l"(a), "l"(b));
}
__device__ __forceinline__ float red2(unsigned long long v) {
    float lo, hi;
    asm("mov.b64 {%0,%1}, %2;" : "=f"(lo), "=f"(hi) : "l"(v));
    return lo + hi;
}

// ---------------------------------------------------------------------------
// init: zero hidden state + barrier slots (must run before each scan)
// ---------------------------------------------------------------------------
__global__ void init_k()
{
    int tid = blockIdx.x * blockDim.x + threadIdx.x;
    if (tid < NBLK) g_arrive[tid] = 0u;
    for (int i = tid; i < BATCH * UN; i += gridDim.x * blockDim.x) {
        g_h[0][i] = 0.f;
        g_h[1][i] = 0.f;
    }
}

// ---------------------------------------------------------------------------
// Input projection GEMM: g_xg[s][col][b] = bias[col] + sum_k A[s,b][k]*W[k][col]
// mode 0: A row (s,b) = emb[tokens[b][s]]   (K = HID)
// mode 1: A row (s,b) = g_y0[s][b][:]       (K = UN)
// Tile: 64(M=batch) x 128(N), BK=8, double-buffered, 256 threads, 8x4/thread.
// ---------------------------------------------------------------------------
__global__ void __launch_bounds__(256) gemm_proj(
    const float* __restrict__ Asrc,
    const int*   __restrict__ tokens,
    const float* __restrict__ Wm,       // [K][G3]
    const float* __restrict__ bias,     // [G3]
    int K, int mode)
{
    __shared__ float As[2][8][64];
    __shared__ float Bs[2][8][128];
    __shared__ float trans[128][68];

    const int s   = blockIdx.y;
    const int n0g = blockIdx.x * 128;
    const int tid = threadIdx.x;

    const int m0 = (tid >> 5) * 8;
    const int n0 = (tid & 31) * 4;

    const int m_a  = tid & 63;
    const int k_a0 = tid >> 6;
    const int k_a1 = k_a0 + 4;
    const float* arow;
    if (mode == 0) {
        int tok = tokens[m_a * SEQ + s];
        arow = Asrc + (size_t)tok * HID;
    } else {
        arow = g_y0 + ((size_t)s * BATCH + m_a) * UN;
    }
    const int k_b = tid >> 5;
    const int n_b = (tid & 31) * 4;

    float acc[8][4];
    #pragma unroll
    for (int i = 0; i < 8; i++)
        #pragma unroll
        for (int j = 0; j < 4; j++) acc[i][j] = 0.f;

    const int Ksteps = (K + 7) / 8;

    As[0][k_a0][m_a] = (k_a0 < K) ? arow[k_a0] : 0.f;
    As[0][k_a1][m_a] = (k_a1 < K) ? arow[k_a1] : 0.f;
    {
        float4 b4 = {0.f, 0.f, 0.f, 0.f};
        if (k_b < K) b4 = *reinterpret_cast<const float4*>(Wm + (size_t)k_b * G3 + n0g + n_b);
        *reinterpret_cast<float4*>(&Bs[0][k_b][n_b]) = b4;
    }
    __syncthreads();

    int buf = 0;
    for (int kt = 0; kt < Ksteps; kt++) {
        float pa0 = 0.f, pa1 = 0.f;
        float4 pb = {0.f, 0.f, 0.f, 0.f};
        const int nk = (kt + 1) * 8;
        if (kt + 1 < Ksteps) {
            int ka = nk + k_a0; if (ka < K) pa0 = arow[ka];
            ka = nk + k_a1;     if (ka < K) pa1 = arow[ka];
            int kb = nk + k_b;
            if (kb < K) pb = *reinterpret_cast<const float4*>(Wm + (size_t)kb * G3 + n0g + n_b);
        }

        #pragma unroll
        for (int k = 0; k < 8; k++) {
            const float4 b4 = *reinterpret_cast<const float4*>(&Bs[buf][k][n0]);
            const float4 a0 = *reinterpret_cast<const float4*>(&As[buf][k][m0]);
            const float4 a1 = *reinterpret_cast<const float4*>(&As[buf][k][m0 + 4]);
            const float av[8] = {a0.x, a0.y, a0.z, a0.w, a1.x, a1.y, a1.z, a1.w};
            const float bv[4] = {b4.x, b4.y, b4.z, b4.w};
            #pragma unroll
            for (int i = 0; i < 8; i++)
                #pragma unroll
                for (int j = 0; j < 4; j++)
                    acc[i][j] = fmaf(av[i], bv[j], acc[i][j]);
        }

        if (kt + 1 < Ksteps) {
            As[buf ^ 1][k_a0][m_a] = pa0;
            As[buf ^ 1][k_a1][m_a] = pa1;
            *reinterpret_cast<float4*>(&Bs[buf ^ 1][k_b][n_b]) = pb;
        }
        __syncthreads();
        buf ^= 1;
    }

    #pragma unroll
    for (int i = 0; i < 8; i++)
        #pragma unroll
        for (int j = 0; j < 4; j++)
            trans[n0 + j][m0 + i] = acc[i][j];
    __syncthreads();

    #pragma unroll
    for (int it = 0; it < 8; it++) {
        int id  = tid + 256 * it;
        int col = id >> 4;
        int m4  = (id & 15) * 4;
        float4 v = *reinterpret_cast<const float4*>(&trans[col][m4]);
        float bb = bias[n0g + col];
        v.x += bb; v.y += bb; v.z += bb; v.w += bb;
        *reinterpret_cast<float4*>(g_xg + ((size_t)s * G3 + n0g + col) * BATCH + m4) = v;
    }
}

// ---------------------------------------------------------------------------
// Persistent GRU scan. 128 blocks x 256 threads (1/SM, wave-1 co-resident).
// Block owns 4 hidden units (12 gate-columns of U in SMEM, loaded once).
// Thread (b, ul): 3 gate dot-products (K=512) via packed f32x2 FMA.
// h tiles register-prefetched; distributed-slot grid barrier per step.
// ---------------------------------------------------------------------------
__global__ void __launch_bounds__(256, 1) gru_scan(
    const float* __restrict__ Um,      // [UN][G3]
    const float* __restrict__ brec,    // [G3]
    int which,
    float* __restrict__ extout)
{
    __shared__ float Us[12][UN];       // 24 KB (z:0-3, r:4-7, h:8-11)
    __shared__ float hs[BATCH][68];    // 17.4 KB (stride 68: 16B-aligned, conflict-free)

    const int tid = threadIdx.x;
    const int b   = tid & 63;
    const int ul  = tid >> 6;
    const int u0  = blockIdx.x * UPB;
    const int u   = u0 + ul;

    for (int idx = tid; idx < 12 * UN; idx += 256) {
        int j = idx >> 9;
        int k = idx & (UN - 1);
        int col = (j >> 2) * UN + u0 + (j & 3);
        Us[j][k] = Um[(size_t)k * G3 + col];
    }
    const float bz = brec[u];
    const float br = brec[UN + u];
    const float bh = brec[2 * UN + u];
    __syncthreads();

    const uint32_t us_base = smem_u32(&Us[0][0]);
    const uint32_t hs_lane = smem_u32(&hs[0][0]) + b * (68 * 4);
    const uint32_t uz_row  = us_base + (0 + ul) * (UN * 4);
    const uint32_t ur_row  = us_base + (4 + ul) * (UN * 4);
    const uint32_t uh_row  = us_base + (8 + ul) * (UN * 4);

    // tile-loader indices: 4 float4 per thread per chunk
    int trow[4], tf4[4];
    #pragma unroll
    for (int i = 0; i < 4; i++) {
        int id = tid + 256 * i;
        trow[i] = id >> 4;
        tf4[i]  = (id & 15) * 4;
    }

    float hprev = 0.f;
    float xz = g_xg[((size_t)0 * G3 + 0 * UN + u) * BATCH + b];
    float xr = g_xg[((size_t)0 * G3 + 1 * UN + u) * BATCH + b];
    float xh = g_xg[((size_t)0 * G3 + 2 * UN + u) * BATCH + b];

    float4 pf[4];

    for (int t = 0; t < SEQ; t++) {
        const float* hr = g_h[t & 1];
        float*       hw = g_h[(t + 1) & 1];

        // load chunk 0 (cannot start before barrier released)
        #pragma unroll
        for (int i = 0; i < 4; i++)
            pf[i] = __ldcv(reinterpret_cast<const float4*>(hr + trow[i] * UN + tf4[i]));

        unsigned long long accz = 0ull, accr = 0ull, acch = 0ull;

        #pragma unroll 1
        for (int kt = 0; kt < 8; kt++) {
            // stage prefetched chunk into SMEM
            #pragma unroll
            for (int i = 0; i < 4; i++)
                *reinterpret_cast<float4*>(&hs[trow[i]][tf4[i]]) = pf[i];
            // issue next chunk's L2 loads (latency hidden behind compute)
            if (kt + 1 < 8) {
                const int nk = (kt + 1) * 64;
                #pragma unroll
                for (int i = 0; i < 4; i++)
                    pf[i] = __ldcv(reinterpret_cast<const float4*>(hr + trow[i] * UN + nk + tf4[i]));
            }
            __syncthreads();

            const uint32_t ko = kt * 64 * 4;
            #pragma unroll
            for (int k = 0; k < 64; k += 4) {
                unsigned long long h0, h1, a0, a1;
                lds2(h0, h1, hs_lane + k * 4);
                lds2(a0, a1, uz_row + ko + k * 4);
                fma2(accz, h0, a0); fma2(accz, h1, a1);
                lds2(a0, a1, ur_row + ko + k * 4);
                fma2(accr, h0, a0); fma2(accr, h1, a1);
                lds2(a0, a1, uh_row + ko + k * 4);
                fma2(acch, h0, a0); fma2(acch, h1, a1);
            }
            __syncthreads();
        }

        const float az = red2(accz);
        const float ar = red2(accr);
        const float ah = red2(acch);

        // gates (Keras reset_after): rg = h@U + b[1]
        const float z  = sigm(xz + az + bz);
        const float r  = sigm(xr + ar + br);
        const float hh = tanhf(xh + r * (ah + bh));
        const float hnew = z * hprev + (1.f - z) * hh;
        hprev = hnew;

        // prefetch next step's gate inputs (latency hidden behind barrier)
        if (t + 1 < SEQ) {
            const float* xgn = g_xg + (size_t)(t + 1) * G3 * BATCH;
            xz = __ldg(xgn + ((size_t)0 * UN + u) * BATCH + b);
            xr = __ldg(xgn + ((size_t)1 * UN + u) * BATCH + b);
            xh = __ldg(xgn + ((size_t)2 * UN + u) * BATCH + b);
        }

        hw[b * UN + u] = hnew;
        if (which == 0) {
            g_y0[((size_t)t * BATCH + b) * UN + u] = hnew;
        } else {
            extout[((size_t)b * SEQ + t) * UN + u] = hnew;
            if (t == SEQ - 1)
                extout[(size_t)BATCH * SEQ * UN + b * UN + u] = hnew;
        }

        // distributed-slot grid barrier: no atomic serialization.
        __threadfence();
        __syncthreads();                       // all threads' h writes fenced
        if (tid == 0)
            *((volatile unsigned*)&g_arrive[blockIdx.x]) = (unsigned)(t + 1);
        if (tid < NBLK) {
            while (*((volatile unsigned*)&g_arrive[tid]) < (unsigned)(t + 1))
                __nanosleep(32);
        }
        __syncthreads();
        __threadfence();
    }
}

// ---------------------------------------------------------------------------
extern "C" void kernel_launch(void* const* d_in, const int* in_sizes, int n_in,
                              void* d_out, int out_size)
{
    const int*   tokens = (const int*)  d_in[0];
    const float* emb    = (const float*)d_in[1];
    const float* W0     = (const float*)d_in[2];
    const float* U0     = (const float*)d_in[3];
    const float* b0     = (const float*)d_in[4];
    const float* W1     = (const float*)d_in[5];
    const float* U1     = (const float*)d_in[6];
    const float* b1     = (const float*)d_in[7];
    float* out = (float*)d_out;

    dim3 gg(G3 / 128, SEQ);

    // layer 0: xg = gather(emb, tokens) @ W0 + b0[0]
    gemm_proj<<<gg, 256>>>(emb, tokens, W0, b0, HID, 0);
    init_k<<<32, 256>>>();
    gru_scan<<<NBLK, 256>>>(U0, b0 + G3, 0, nullptr);

    // layer 1: xg = y0 @ W1 + b1[0]   (g_xg reused)
    gemm_proj<<<gg, 256>>>(nullptr, nullptr, W1, b1, UN, 1);
    init_k<<<32, 256>>>();
    gru_scan<<<NBLK, 256>>>(U1, b1 + G3, 1, out);
}